// round 7
// baseline (speedup 1.0000x reference)
#include <cuda_runtime.h>

#define NN     100000
#define EE     1600000
#define GG     256
#define EMB_D  128
#define HID_D  64

// ---------------- scratch (device globals; no allocations allowed) ----------
__device__ float4 g_xw[NN * 16];        // [N,64] y = (x@W)*dinv  (float4 rows)
__device__ float4 g_h [NN * 16];        // [N,64] gather/relu output
__device__ int    g_csr[EE];            // CSR src indices (by dst)
__device__ int    g_rowstart[NN + 1];   // CSR row offsets
__device__ int    g_cnt[NN];            // in-degree histogram
__device__ int    g_fill[NN];           // scatter fill counters
__device__ float  g_dinv[NN];           // 1/sqrt(deg+1)
__device__ float4 g_pooled[GG * 16];    // [G,64] pooled sums
__device__ int    g_gcount[GG];         // nodes per graph

// packed fp32x2 FMA (sm_100+): d = a*b + d  (two independent fp32 lanes)
__device__ __forceinline__ void fma2(unsigned long long& d,
                                     unsigned long long a,
                                     unsigned long long b) {
    asm("fma.rn.f32x2 %0, %1, %2, %0;" : "+l"(d) : "l"(a), "l"(b));
}

// ---------------- init / CSR build ------------------------------------------
__global__ void zero_kernel() {
    int i = blockIdx.x * blockDim.x + threadIdx.x;
    if (i < NN) { g_cnt[i] = 0; g_fill[i] = 0; }
    if (i < GG * 16) g_pooled[i] = make_float4(0.f, 0.f, 0.f, 0.f);
    if (i < GG) g_gcount[i] = 0;
}

// nodes-per-graph histogram; batch is sorted so most warps hit one address ->
// ptxas warp-aggregates (REDUX) these atomics.
__global__ void count_kernel(const int* __restrict__ batch) {
    int i = blockIdx.x * blockDim.x + threadIdx.x;
    if (i < NN) atomicAdd(&g_gcount[batch[i]], 1);
}

__global__ void hist_kernel(const int* __restrict__ dst) {
    int e = blockIdx.x * blockDim.x + threadIdx.x;
    if (e < EE) atomicAdd(&g_cnt[dst[e]], 1);
}

// single-block exclusive scan over g_cnt -> g_rowstart; also emits g_dinv.
__global__ void __launch_bounds__(1024) scan_kernel() {
    __shared__ int wsum[32];
    __shared__ int wexcl[33];
    int tid = threadIdx.x, lane = tid & 31, wid = tid >> 5;
    int carry = 0;
    for (int base = 0; base < NN; base += 4096) {
        int i0 = base + tid * 4;
        int v0 = (i0     < NN) ? g_cnt[i0]     : 0;
        int v1 = (i0 + 1 < NN) ? g_cnt[i0 + 1] : 0;
        int v2 = (i0 + 2 < NN) ? g_cnt[i0 + 2] : 0;
        int v3 = (i0 + 3 < NN) ? g_cnt[i0 + 3] : 0;
        if (i0     < NN) g_dinv[i0]     = rsqrtf((float)v0 + 1.0f);
        if (i0 + 1 < NN) g_dinv[i0 + 1] = rsqrtf((float)v1 + 1.0f);
        if (i0 + 2 < NN) g_dinv[i0 + 2] = rsqrtf((float)v2 + 1.0f);
        if (i0 + 3 < NN) g_dinv[i0 + 3] = rsqrtf((float)v3 + 1.0f);
        int ts = v0 + v1 + v2 + v3;
        int incl = ts;
        #pragma unroll
        for (int off = 1; off < 32; off <<= 1) {
            int t = __shfl_up_sync(0xffffffffu, incl, off);
            if (lane >= off) incl += t;
        }
        if (lane == 31) wsum[wid] = incl;
        __syncthreads();
        if (wid == 0) {
            int s = wsum[lane];
            int si = s;
            #pragma unroll
            for (int off = 1; off < 32; off <<= 1) {
                int t = __shfl_up_sync(0xffffffffu, si, off);
                if (lane >= off) si += t;
            }
            wexcl[lane] = si - s;
            if (lane == 31) wexcl[32] = si;
        }
        __syncthreads();
        int e0 = carry + wexcl[wid] + (incl - ts);
        int e1 = e0 + v0, e2 = e1 + v1, e3 = e2 + v2;
        if (i0     < NN) g_rowstart[i0]     = e0;
        if (i0 + 1 < NN) g_rowstart[i0 + 1] = e1;
        if (i0 + 2 < NN) g_rowstart[i0 + 2] = e2;
        if (i0 + 3 < NN) g_rowstart[i0 + 3] = e3;
        carry += wexcl[32];
        __syncthreads();
    }
    if (tid == 0) g_rowstart[NN] = carry;
}

__global__ void scatter_kernel(const int* __restrict__ src,
                               const int* __restrict__ dst) {
    int e = blockIdx.x * blockDim.x + threadIdx.x;
    if (e < EE) {
        int d = dst[e];
        int pos = g_rowstart[d] + atomicAdd(&g_fill[d], 1);
        g_csr[pos] = src[e];
    }
}

// ---------------- GEMM 1: y = (emb[x_ids] @ W1) * dinv  (128 -> 64) ---------
__global__ void __launch_bounds__(192) gemm1_kernel(const int* __restrict__ x_ids,
                                                    const float* __restrict__ emb,
                                                    const float* __restrict__ W) {
    __shared__ float Wt[64 * 130];
    __shared__ float xs[24 * 128];
    __shared__ int ids[24];
    int tid = threadIdx.x;
    for (int i = tid; i < EMB_D * HID_D; i += 192) {
        int k = i >> 6, f = i & 63;
        Wt[f * 130 + k] = W[i];
    }
    int grp = tid >> 6, f = tid & 63;
    float* xwf = reinterpret_cast<float*>(g_xw);
    for (int nb = blockIdx.x * 24; nb < NN; nb += gridDim.x * 24) {
        __syncthreads();
        if (tid < 24) { int n = nb + tid; ids[tid] = (n < NN) ? x_ids[n] : 0; }
        __syncthreads();
        for (int i = tid; i < 24 * 128; i += 192) {
            int nl = i >> 7, k = i & 127;
            xs[i] = emb[ids[nl] * 128 + k];
        }
        __syncthreads();
        unsigned long long acc[8];
        #pragma unroll
        for (int n = 0; n < 8; n++) acc[n] = 0ull;
        const float* xb  = &xs[(grp * 8) * 128];
        const float* wrw = &Wt[f * 130];
        #pragma unroll 4
        for (int kp = 0; kp < 64; kp++) {
            unsigned long long w2 =
                *reinterpret_cast<const unsigned long long*>(&wrw[2 * kp]);
            #pragma unroll
            for (int n = 0; n < 8; n++) {
                unsigned long long x2 =
                    *reinterpret_cast<const unsigned long long*>(&xb[n * 128 + 2 * kp]);
                fma2(acc[n], w2, x2);
            }
        }
        #pragma unroll
        for (int n = 0; n < 8; n++) {
            int node = nb + grp * 8 + n;
            if (node < NN) {
                float lo = __uint_as_float((unsigned)(acc[n] & 0xffffffffu));
                float hi = __uint_as_float((unsigned)(acc[n] >> 32));
                xwf[node * 64 + f] = (lo + hi) * g_dinv[node];
            }
        }
    }
}

// ---------------- GEMM 64->64: y = (g_h @ W) * dinv --------------------------
__global__ void __launch_bounds__(256) gemm64_kernel(const float* __restrict__ W) {
    __shared__ float Wt[64 * 66];
    __shared__ float xs[32 * 64];
    int tid = threadIdx.x;
    for (int i = tid; i < 64 * 64; i += 256) {
        int k = i >> 6, f = i & 63;
        Wt[f * 66 + k] = W[i];
    }
    int grp = tid >> 6, f = tid & 63;
    const float* X = reinterpret_cast<const float*>(g_h);
    float* xwf = reinterpret_cast<float*>(g_xw);
    for (int nb = blockIdx.x * 32; nb < NN; nb += gridDim.x * 32) {
        __syncthreads();
        for (int i = tid; i < 32 * 64; i += 256) {
            int nl = i >> 6, k = i & 63;
            int n = nb + nl;
            xs[i] = (n < NN) ? X[n * 64 + k] : 0.f;
        }
        __syncthreads();
        unsigned long long acc[8];
        #pragma unroll
        for (int n = 0; n < 8; n++) acc[n] = 0ull;
        const float* xb  = &xs[(grp * 8) * 64];
        const float* wrw = &Wt[f * 66];
        #pragma unroll 4
        for (int kp = 0; kp < 32; kp++) {
            unsigned long long w2 =
                *reinterpret_cast<const unsigned long long*>(&wrw[2 * kp]);
            #pragma unroll
            for (int n = 0; n < 8; n++) {
                unsigned long long x2 =
                    *reinterpret_cast<const unsigned long long*>(&xb[n * 64 + 2 * kp]);
                fma2(acc[n], w2, x2);
            }
        }
        #pragma unroll
        for (int n = 0; n < 8; n++) {
            int node = nb + grp * 8 + n;
            if (node < NN) {
                float lo = __uint_as_float((unsigned)(acc[n] & 0xffffffffu));
                float hi = __uint_as_float((unsigned)(acc[n] >> 32));
                xwf[node * 64 + f] = (lo + hi) * g_dinv[node];
            }
        }
    }
}

// ---------------- CSR gather: h = relu(dinv*(y_self + sum y[src]) + b) ------
// 16 threads per node, one float4 per thread, edge loop unrolled x4 (MLP=4).
// LAST: skip writing g_h; atomically accumulate into pooled sums instead.
template<bool LAST>
__global__ void gather_kernel(const float* __restrict__ bias,
                              const int* __restrict__ batch) {
    int t = blockIdx.x * blockDim.x + threadIdx.x;
    int node = t >> 4, c = t & 15;
    if (node >= NN) return;
    const float4* __restrict__ y = g_xw;
    float4 a = y[node * 16 + c];                  // self term
    int p  = g_rowstart[node];
    int pe = g_rowstart[node + 1];
    for (; p + 4 <= pe; p += 4) {
        int s0 = g_csr[p], s1 = g_csr[p + 1], s2 = g_csr[p + 2], s3 = g_csr[p + 3];
        float4 v0 = y[s0 * 16 + c];
        float4 v1 = y[s1 * 16 + c];
        float4 v2 = y[s2 * 16 + c];
        float4 v3 = y[s3 * 16 + c];
        v0.x += v1.x; v0.y += v1.y; v0.z += v1.z; v0.w += v1.w;
        v2.x += v3.x; v2.y += v3.y; v2.z += v3.z; v2.w += v3.w;
        a.x += v0.x + v2.x; a.y += v0.y + v2.y;
        a.z += v0.z + v2.z; a.w += v0.w + v2.w;
    }
    for (; p < pe; ++p) {
        int s = g_csr[p];
        float4 v = y[s * 16 + c];
        a.x += v.x; a.y += v.y; a.z += v.z; a.w += v.w;
    }
    float dn = g_dinv[node];
    float4 bb = reinterpret_cast<const float4*>(bias)[c];
    a.x = fmaxf(fmaf(a.x, dn, bb.x), 0.f);
    a.y = fmaxf(fmaf(a.y, dn, bb.y), 0.f);
    a.z = fmaxf(fmaf(a.z, dn, bb.z), 0.f);
    a.w = fmaxf(fmaf(a.w, dn, bb.w), 0.f);
    if (!LAST) {
        g_h[node * 16 + c] = a;
    } else {
        int g = batch[node];
        float* pp = reinterpret_cast<float*>(g_pooled) + g * 64 + c * 4;
        atomicAdd(pp + 0, a.x);
        atomicAdd(pp + 1, a.y);
        atomicAdd(pp + 2, a.z);
        atomicAdd(pp + 3, a.w);
    }
}

// ---------------- final MLP + sigmoid (thread per graph) --------------------
__global__ void __launch_bounds__(32) mlp_kernel(const float* __restrict__ Wf1,
                                                 const float* __restrict__ bf1,
                                                 const float* __restrict__ Wf2,
                                                 const float* __restrict__ bf2,
                                                 float* __restrict__ out) {
    __shared__ float Ws[64 * 64];
    __shared__ float b1s[64];
    __shared__ float w2s[64];
    int tid = threadIdx.x;
    for (int i = tid; i < 64 * 64; i += 32) Ws[i] = Wf1[i];
    for (int i = tid; i < 64; i += 32) { b1s[i] = bf1[i]; w2s[i] = Wf2[i]; }
    __syncthreads();
    int g = blockIdx.x * 32 + tid;
    float cnt = fmaxf((float)g_gcount[g], 1.f);
    float inv = 1.f / cnt;
    const float* pooled = reinterpret_cast<const float*>(g_pooled) + g * 64;
    float p[64];
    #pragma unroll
    for (int k = 0; k < 64; k++) p[k] = pooled[k] * inv;
    float o = bf2[0];
    for (int j = 0; j < 64; j++) {
        float hj = b1s[j];
        #pragma unroll
        for (int k = 0; k < 64; k++) hj = fmaf(p[k], Ws[k * 64 + j], hj);
        o = fmaf(fmaxf(hj, 0.f), w2s[j], o);
    }
    out[g] = 1.f / (1.f + expf(-o));
}

// ---------------- launch ----------------------------------------------------
extern "C" void kernel_launch(void* const* d_in, const int* in_sizes, int n_in,
                              void* d_out, int out_size) {
    const int*   x_ids = (const int*)d_in[0];
    const int*   ei    = (const int*)d_in[1];
    const int*   batch = (const int*)d_in[2];
    const float* emb   = (const float*)d_in[3];
    const float* W1    = (const float*)d_in[4];
    const float* b1    = (const float*)d_in[5];
    const float* W2    = (const float*)d_in[6];
    const float* b2    = (const float*)d_in[7];
    const float* W3    = (const float*)d_in[8];
    const float* b3    = (const float*)d_in[9];
    const float* Wf1   = (const float*)d_in[10];
    const float* bf1   = (const float*)d_in[11];
    const float* Wf2   = (const float*)d_in[12];
    const float* bf2   = (const float*)d_in[13];
    float* out = (float*)d_out;

    const int* src  = ei;
    const int* dstp = ei + EE;

    int nblkN = (NN + 255) / 256;
    int nblkE = (EE + 255) / 256;
    int nblkG = (NN * 16 + 255) / 256;

    // CSR build
    zero_kernel<<<nblkN, 256>>>();
    count_kernel<<<nblkN, 256>>>(batch);
    hist_kernel<<<nblkE, 256>>>(dstp);
    scan_kernel<<<1, 1024>>>();          // also computes g_dinv
    scatter_kernel<<<nblkE, 256>>>(src, dstp);

    // layer 1
    gemm1_kernel<<<740, 192>>>(x_ids, emb, W1);
    gather_kernel<false><<<nblkG, 256>>>(b1, batch);
    // layer 2
    gemm64_kernel<<<1184, 256>>>(W2);
    gather_kernel<false><<<nblkG, 256>>>(b2, batch);
    // layer 3 (+ fused pooling)
    gemm64_kernel<<<1184, 256>>>(W3);
    gather_kernel<true><<<nblkG, 256>>>(b3, batch);

    // head
    mlp_kernel<<<8, 32>>>(Wf1, bf1, Wf2, bf2, out);
}

// round 8
// speedup vs baseline: 1.0956x; 1.0956x over previous
#include <cuda_runtime.h>

#define NN     100000
#define EE     1600000
#define GG     256
#define EMB_D  128
#define HID_D  64
#define SCHUNK 1024
#define SNB    ((NN + SCHUNK - 1) / SCHUNK)   // 98 scan blocks

// ---------------- scratch (device globals; no allocations allowed) ----------
__device__ float4 g_xw[NN * 16];        // [N,64] y = (x@W)*dinv  (float4 rows)
__device__ float4 g_h [NN * 16];        // [N,64] gather/relu output
__device__ int    g_csr[EE];            // CSR src indices (by dst)
__device__ int    g_rowstart[NN + 1];   // CSR row offsets
__device__ int    g_cnt[NN];            // in-degree histogram
__device__ int    g_fill[NN];           // scatter fill counters
__device__ float  g_dinv[NN];           // 1/sqrt(deg+1)
__device__ float4 g_pooled[GG * 16];    // [G,64] pooled sums
__device__ int    g_gcount[GG];         // nodes per graph
__device__ int    g_blocksum[SNB];      // scan phase-1 partial sums
__device__ int    g_blockoff[SNB];      // scan phase-2 block offsets

// packed fp32x2 FMA (sm_100+): d = a*b + d  (two independent fp32 lanes)
__device__ __forceinline__ void fma2(unsigned long long& d,
                                     unsigned long long a,
                                     unsigned long long b) {
    asm("fma.rn.f32x2 %0, %1, %2, %0;" : "+l"(d) : "l"(a), "l"(b));
}

// ---------------- init / CSR build ------------------------------------------
__global__ void zero_kernel() {
    int i = blockIdx.x * blockDim.x + threadIdx.x;
    if (i < NN) { g_cnt[i] = 0; g_fill[i] = 0; }
    if (i < GG * 16) g_pooled[i] = make_float4(0.f, 0.f, 0.f, 0.f);
    if (i < GG) g_gcount[i] = 0;
}

// nodes-per-graph histogram; batch is sorted -> warp-aggregated atomics.
__global__ void count_kernel(const int* __restrict__ batch) {
    int i = blockIdx.x * blockDim.x + threadIdx.x;
    if (i < NN) atomicAdd(&g_gcount[batch[i]], 1);
}

__global__ void hist_kernel(const int* __restrict__ dst) {
    int e = blockIdx.x * blockDim.x + threadIdx.x;
    if (e < EE) atomicAdd(&g_cnt[dst[e]], 1);
}

// ---- parallel scan, phase 1: per-block sums (+ dinv) ------------------------
__global__ void __launch_bounds__(256) scan_part_kernel() {
    __shared__ int wsum[8];
    int b = blockIdx.x, tid = threadIdx.x, lane = tid & 31, wid = tid >> 5;
    int i0 = b * SCHUNK + tid * 4;
    int v0 = (i0     < NN) ? g_cnt[i0]     : 0;
    int v1 = (i0 + 1 < NN) ? g_cnt[i0 + 1] : 0;
    int v2 = (i0 + 2 < NN) ? g_cnt[i0 + 2] : 0;
    int v3 = (i0 + 3 < NN) ? g_cnt[i0 + 3] : 0;
    if (i0     < NN) g_dinv[i0]     = rsqrtf((float)v0 + 1.0f);
    if (i0 + 1 < NN) g_dinv[i0 + 1] = rsqrtf((float)v1 + 1.0f);
    if (i0 + 2 < NN) g_dinv[i0 + 2] = rsqrtf((float)v2 + 1.0f);
    if (i0 + 3 < NN) g_dinv[i0 + 3] = rsqrtf((float)v3 + 1.0f);
    int ts = v0 + v1 + v2 + v3;
    #pragma unroll
    for (int off = 16; off > 0; off >>= 1)
        ts += __shfl_down_sync(0xffffffffu, ts, off);
    if (lane == 0) wsum[wid] = ts;
    __syncthreads();
    if (tid == 0) {
        int s = 0;
        #pragma unroll
        for (int w = 0; w < 8; w++) s += wsum[w];
        g_blocksum[b] = s;
    }
}

// ---- phase 2: exclusive scan of SNB block sums (1 block) --------------------
__global__ void __launch_bounds__(128) scan_mid_kernel() {
    __shared__ int ws[4];
    int tid = threadIdx.x, lane = tid & 31, wid = tid >> 5;
    int v = (tid < SNB) ? g_blocksum[tid] : 0;
    int incl = v;
    #pragma unroll
    for (int off = 1; off < 32; off <<= 1) {
        int t = __shfl_up_sync(0xffffffffu, incl, off);
        if (lane >= off) incl += t;
    }
    if (lane == 31) ws[wid] = incl;
    __syncthreads();
    int woff = 0;
    for (int w = 0; w < wid; w++) woff += ws[w];
    if (tid < SNB) g_blockoff[tid] = woff + incl - v;
}

// ---- phase 3: block-local scan + offset -> g_rowstart -----------------------
__global__ void __launch_bounds__(256) scan_final_kernel() {
    __shared__ int wsum[8];
    int b = blockIdx.x, tid = threadIdx.x, lane = tid & 31, wid = tid >> 5;
    int i0 = b * SCHUNK + tid * 4;
    int v0 = (i0     < NN) ? g_cnt[i0]     : 0;
    int v1 = (i0 + 1 < NN) ? g_cnt[i0 + 1] : 0;
    int v2 = (i0 + 2 < NN) ? g_cnt[i0 + 2] : 0;
    int v3 = (i0 + 3 < NN) ? g_cnt[i0 + 3] : 0;
    int ts = v0 + v1 + v2 + v3;
    int incl = ts;
    #pragma unroll
    for (int off = 1; off < 32; off <<= 1) {
        int t = __shfl_up_sync(0xffffffffu, incl, off);
        if (lane >= off) incl += t;
    }
    if (lane == 31) wsum[wid] = incl;
    __syncthreads();
    int woff = 0;
    for (int w = 0; w < wid; w++) woff += wsum[w];
    int e0 = g_blockoff[b] + woff + (incl - ts);
    int e1 = e0 + v0, e2 = e1 + v1, e3 = e2 + v2;
    if (i0     < NN) g_rowstart[i0]     = e0;
    if (i0 + 1 < NN) g_rowstart[i0 + 1] = e1;
    if (i0 + 2 < NN) g_rowstart[i0 + 2] = e2;
    if (i0 + 3 < NN) g_rowstart[i0 + 3] = e3;
    if (b == 0 && tid == 0) g_rowstart[NN] = EE;   // total is compile-time known
}

__global__ void scatter_kernel(const int* __restrict__ src,
                               const int* __restrict__ dst) {
    int e = blockIdx.x * blockDim.x + threadIdx.x;
    if (e < EE) {
        int d = dst[e];
        int pos = g_rowstart[d] + atomicAdd(&g_fill[d], 1);
        g_csr[pos] = src[e];
    }
}

// ---------------- GEMM 1: y = (emb[x_ids] @ W1) * dinv  (128 -> 64) ---------
__global__ void __launch_bounds__(192) gemm1_kernel(const int* __restrict__ x_ids,
                                                    const float* __restrict__ emb,
                                                    const float* __restrict__ W) {
    __shared__ float Wt[64 * 130];
    __shared__ float xs[24 * 128];
    __shared__ int ids[24];
    int tid = threadIdx.x;
    for (int i = tid; i < EMB_D * HID_D; i += 192) {
        int k = i >> 6, f = i & 63;
        Wt[f * 130 + k] = W[i];
    }
    int grp = tid >> 6, f = tid & 63;
    float* xwf = reinterpret_cast<float*>(g_xw);
    for (int nb = blockIdx.x * 24; nb < NN; nb += gridDim.x * 24) {
        __syncthreads();
        if (tid < 24) { int n = nb + tid; ids[tid] = (n < NN) ? x_ids[n] : 0; }
        __syncthreads();
        for (int i = tid; i < 24 * 128; i += 192) {
            int nl = i >> 7, k = i & 127;
            xs[i] = emb[ids[nl] * 128 + k];
        }
        __syncthreads();
        unsigned long long acc[8];
        #pragma unroll
        for (int n = 0; n < 8; n++) acc[n] = 0ull;
        const float* xb  = &xs[(grp * 8) * 128];
        const float* wrw = &Wt[f * 130];
        #pragma unroll 4
        for (int kp = 0; kp < 64; kp++) {
            unsigned long long w2 =
                *reinterpret_cast<const unsigned long long*>(&wrw[2 * kp]);
            #pragma unroll
            for (int n = 0; n < 8; n++) {
                unsigned long long x2 =
                    *reinterpret_cast<const unsigned long long*>(&xb[n * 128 + 2 * kp]);
                fma2(acc[n], w2, x2);
            }
        }
        #pragma unroll
        for (int n = 0; n < 8; n++) {
            int node = nb + grp * 8 + n;
            if (node < NN) {
                float lo = __uint_as_float((unsigned)(acc[n] & 0xffffffffu));
                float hi = __uint_as_float((unsigned)(acc[n] >> 32));
                xwf[node * 64 + f] = (lo + hi) * g_dinv[node];
            }
        }
    }
}

// ---------------- GEMM 64->64: y = (g_h @ W) * dinv --------------------------
__global__ void __launch_bounds__(256) gemm64_kernel(const float* __restrict__ W) {
    __shared__ float Wt[64 * 66];
    __shared__ float xs[32 * 64];
    int tid = threadIdx.x;
    for (int i = tid; i < 64 * 64; i += 256) {
        int k = i >> 6, f = i & 63;
        Wt[f * 66 + k] = W[i];
    }
    int grp = tid >> 6, f = tid & 63;
    const float* X = reinterpret_cast<const float*>(g_h);
    float* xwf = reinterpret_cast<float*>(g_xw);
    for (int nb = blockIdx.x * 32; nb < NN; nb += gridDim.x * 32) {
        __syncthreads();
        for (int i = tid; i < 32 * 64; i += 256) {
            int nl = i >> 6, k = i & 63;
            int n = nb + nl;
            xs[i] = (n < NN) ? X[n * 64 + k] : 0.f;
        }
        __syncthreads();
        unsigned long long acc[8];
        #pragma unroll
        for (int n = 0; n < 8; n++) acc[n] = 0ull;
        const float* xb  = &xs[(grp * 8) * 64];
        const float* wrw = &Wt[f * 66];
        #pragma unroll 4
        for (int kp = 0; kp < 32; kp++) {
            unsigned long long w2 =
                *reinterpret_cast<const unsigned long long*>(&wrw[2 * kp]);
            #pragma unroll
            for (int n = 0; n < 8; n++) {
                unsigned long long x2 =
                    *reinterpret_cast<const unsigned long long*>(&xb[n * 64 + 2 * kp]);
                fma2(acc[n], w2, x2);
            }
        }
        #pragma unroll
        for (int n = 0; n < 8; n++) {
            int node = nb + grp * 8 + n;
            if (node < NN) {
                float lo = __uint_as_float((unsigned)(acc[n] & 0xffffffffu));
                float hi = __uint_as_float((unsigned)(acc[n] >> 32));
                xwf[node * 64 + f] = (lo + hi) * g_dinv[node];
            }
        }
    }
}

// ---------------- CSR gather: h = relu(dinv*(y_self + sum y[src]) + b) ------
// 16 threads per node, one float4 per thread, edge loop unrolled x4 (MLP=4).
// LAST: skip writing g_h; atomically accumulate into pooled sums instead.
template<bool LAST>
__global__ void gather_kernel(const float* __restrict__ bias,
                              const int* __restrict__ batch) {
    int t = blockIdx.x * blockDim.x + threadIdx.x;
    int node = t >> 4, c = t & 15;
    if (node >= NN) return;
    const float4* __restrict__ y = g_xw;
    float4 a = y[node * 16 + c];                  // self term
    int p  = g_rowstart[node];
    int pe = g_rowstart[node + 1];
    for (; p + 4 <= pe; p += 4) {
        int s0 = g_csr[p], s1 = g_csr[p + 1], s2 = g_csr[p + 2], s3 = g_csr[p + 3];
        float4 v0 = y[s0 * 16 + c];
        float4 v1 = y[s1 * 16 + c];
        float4 v2 = y[s2 * 16 + c];
        float4 v3 = y[s3 * 16 + c];
        v0.x += v1.x; v0.y += v1.y; v0.z += v1.z; v0.w += v1.w;
        v2.x += v3.x; v2.y += v3.y; v2.z += v3.z; v2.w += v3.w;
        a.x += v0.x + v2.x; a.y += v0.y + v2.y;
        a.z += v0.z + v2.z; a.w += v0.w + v2.w;
    }
    for (; p < pe; ++p) {
        int s = g_csr[p];
        float4 v = y[s * 16 + c];
        a.x += v.x; a.y += v.y; a.z += v.z; a.w += v.w;
    }
    float dn = g_dinv[node];
    float4 bb = reinterpret_cast<const float4*>(bias)[c];
    a.x = fmaxf(fmaf(a.x, dn, bb.x), 0.f);
    a.y = fmaxf(fmaf(a.y, dn, bb.y), 0.f);
    a.z = fmaxf(fmaf(a.z, dn, bb.z), 0.f);
    a.w = fmaxf(fmaf(a.w, dn, bb.w), 0.f);
    if (!LAST) {
        g_h[node * 16 + c] = a;
    } else {
        int g = batch[node];
        float* pp = reinterpret_cast<float*>(g_pooled) + g * 64 + c * 4;
        atomicAdd(pp + 0, a.x);
        atomicAdd(pp + 1, a.y);
        atomicAdd(pp + 2, a.z);
        atomicAdd(pp + 3, a.w);
    }
}

// ---------------- final MLP + sigmoid (thread per graph) --------------------
__global__ void __launch_bounds__(32) mlp_kernel(const float* __restrict__ Wf1,
                                                 const float* __restrict__ bf1,
                                                 const float* __restrict__ Wf2,
                                                 const float* __restrict__ bf2,
                                                 float* __restrict__ out) {
    __shared__ float Ws[64 * 64];
    __shared__ float b1s[64];
    __shared__ float w2s[64];
    int tid = threadIdx.x;
    for (int i = tid; i < 64 * 64; i += 32) Ws[i] = Wf1[i];
    for (int i = tid; i < 64; i += 32) { b1s[i] = bf1[i]; w2s[i] = Wf2[i]; }
    __syncthreads();
    int g = blockIdx.x * 32 + tid;
    float cnt = fmaxf((float)g_gcount[g], 1.f);
    float inv = 1.f / cnt;
    const float* pooled = reinterpret_cast<const float*>(g_pooled) + g * 64;
    float p[64];
    #pragma unroll
    for (int k = 0; k < 64; k++) p[k] = pooled[k] * inv;
    float o = bf2[0];
    for (int j = 0; j < 64; j++) {
        float hj = b1s[j];
        #pragma unroll
        for (int k = 0; k < 64; k++) hj = fmaf(p[k], Ws[k * 64 + j], hj);
        o = fmaf(fmaxf(hj, 0.f), w2s[j], o);
    }
    out[g] = 1.f / (1.f + expf(-o));
}

// ---------------- launch ----------------------------------------------------
extern "C" void kernel_launch(void* const* d_in, const int* in_sizes, int n_in,
                              void* d_out, int out_size) {
    const int*   x_ids = (const int*)d_in[0];
    const int*   ei    = (const int*)d_in[1];
    const int*   batch = (const int*)d_in[2];
    const float* emb   = (const float*)d_in[3];
    const float* W1    = (const float*)d_in[4];
    const float* b1    = (const float*)d_in[5];
    const float* W2    = (const float*)d_in[6];
    const float* b2    = (const float*)d_in[7];
    const float* W3    = (const float*)d_in[8];
    const float* b3    = (const float*)d_in[9];
    const float* Wf1   = (const float*)d_in[10];
    const float* bf1   = (const float*)d_in[11];
    const float* Wf2   = (const float*)d_in[12];
    const float* bf2   = (const float*)d_in[13];
    float* out = (float*)d_out;

    const int* src  = ei;
    const int* dstp = ei + EE;

    int nblkN = (NN + 255) / 256;
    int nblkE = (EE + 255) / 256;
    int nblkG = (NN * 16 + 255) / 256;

    // CSR build (parallel 3-phase scan replaces the single-block scan)
    zero_kernel<<<nblkN, 256>>>();
    count_kernel<<<nblkN, 256>>>(batch);
    hist_kernel<<<nblkE, 256>>>(dstp);
    scan_part_kernel<<<SNB, 256>>>();    // also computes g_dinv
    scan_mid_kernel<<<1, 128>>>();
    scan_final_kernel<<<SNB, 256>>>();
    scatter_kernel<<<nblkE, 256>>>(src, dstp);

    // layer 1
    gemm1_kernel<<<740, 192>>>(x_ids, emb, W1);
    gather_kernel<false><<<nblkG, 256>>>(b1, batch);
    // layer 2
    gemm64_kernel<<<1184, 256>>>(W2);
    gather_kernel<false><<<nblkG, 256>>>(b2, batch);
    // layer 3 (+ fused pooling)
    gemm64_kernel<<<1184, 256>>>(W3);
    gather_kernel<true><<<nblkG, 256>>>(b3, batch);

    // head
    mlp_kernel<<<8, 32>>>(Wf1, bf1, Wf2, bf2, out);
}

// round 11
// speedup vs baseline: 1.1516x; 1.0511x over previous
#include <cuda_runtime.h>

#define NN     100000
#define EE     1600000
#define GG     256
#define EMB_D  128
#define HID_D  64
#define SCHUNK 1024
#define SNB    ((NN + SCHUNK - 1) / SCHUNK)   // 98 scan blocks

// ---------------- scratch (device globals; no allocations allowed) ----------
__device__ float4 g_xw[NN * 16];        // [N,64] y = (x@W)*dinv  (float4 rows)
__device__ float4 g_h [NN * 16];        // [N,64] gather/relu output
__device__ int    g_csr[EE];            // CSR src indices (by dst)
__device__ int    g_rowstart[NN + 1];   // CSR row offsets
__device__ int    g_cnt[NN];            // in-degree histogram
__device__ int    g_fill[NN];           // scatter fill counters
__device__ float  g_dinv[NN];           // 1/sqrt(deg+1)
__device__ float4 g_pooled[GG * 16];    // [G,64] pooled sums
__device__ int    g_gcount[GG];         // nodes per graph
__device__ int    g_blocksum[SNB];      // scan phase-1 partial sums
__device__ int    g_blockoff[SNB];      // scan phase-2 block offsets

// packed fp32x2 FMA (sm_100+): d = a*b + d  (two independent fp32 lanes)
__device__ __forceinline__ void fma2(unsigned long long& d,
                                     unsigned long long a,
                                     unsigned long long b) {
    asm("fma.rn.f32x2 %0, %1, %2, %0;" : "+l"(d) : "l"(a), "l"(b));
}

// ---------------- init / CSR build ------------------------------------------
__global__ void zero_kernel() {
    int i = blockIdx.x * blockDim.x + threadIdx.x;
    if (i < NN) { g_cnt[i] = 0; g_fill[i] = 0; }
    if (i < GG * 16) g_pooled[i] = make_float4(0.f, 0.f, 0.f, 0.f);
    if (i < GG) g_gcount[i] = 0;
}

// nodes-per-graph histogram; batch is sorted -> warp-aggregated atomics.
__global__ void count_kernel(const int* __restrict__ batch) {
    int i = blockIdx.x * blockDim.x + threadIdx.x;
    if (i < NN) atomicAdd(&g_gcount[batch[i]], 1);
}

__global__ void hist_kernel(const int* __restrict__ dst) {
    int e = blockIdx.x * blockDim.x + threadIdx.x;
    if (e < EE) atomicAdd(&g_cnt[dst[e]], 1);
}

// ---- parallel scan, phase 1: per-block sums (+ dinv) ------------------------
__global__ void __launch_bounds__(256) scan_part_kernel() {
    __shared__ int wsum[8];
    int b = blockIdx.x, tid = threadIdx.x, lane = tid & 31, wid = tid >> 5;
    int i0 = b * SCHUNK + tid * 4;
    int v0 = (i0     < NN) ? g_cnt[i0]     : 0;
    int v1 = (i0 + 1 < NN) ? g_cnt[i0 + 1] : 0;
    int v2 = (i0 + 2 < NN) ? g_cnt[i0 + 2] : 0;
    int v3 = (i0 + 3 < NN) ? g_cnt[i0 + 3] : 0;
    if (i0     < NN) g_dinv[i0]     = rsqrtf((float)v0 + 1.0f);
    if (i0 + 1 < NN) g_dinv[i0 + 1] = rsqrtf((float)v1 + 1.0f);
    if (i0 + 2 < NN) g_dinv[i0 + 2] = rsqrtf((float)v2 + 1.0f);
    if (i0 + 3 < NN) g_dinv[i0 + 3] = rsqrtf((float)v3 + 1.0f);
    int ts = v0 + v1 + v2 + v3;
    #pragma unroll
    for (int off = 16; off > 0; off >>= 1)
        ts += __shfl_down_sync(0xffffffffu, ts, off);
    if (lane == 0) wsum[wid] = ts;
    __syncthreads();
    if (tid == 0) {
        int s = 0;
        #pragma unroll
        for (int w = 0; w < 8; w++) s += wsum[w];
        g_blocksum[b] = s;
    }
}

// ---- phase 2: exclusive scan of SNB block sums (1 block) --------------------
__global__ void __launch_bounds__(128) scan_mid_kernel() {
    __shared__ int ws[4];
    int tid = threadIdx.x, lane = tid & 31, wid = tid >> 5;
    int v = (tid < SNB) ? g_blocksum[tid] : 0;
    int incl = v;
    #pragma unroll
    for (int off = 1; off < 32; off <<= 1) {
        int t = __shfl_up_sync(0xffffffffu, incl, off);
        if (lane >= off) incl += t;
    }
    if (lane == 31) ws[wid] = incl;
    __syncthreads();
    int woff = 0;
    for (int w = 0; w < wid; w++) woff += ws[w];
    if (tid < SNB) g_blockoff[tid] = woff + incl - v;
}

// ---- phase 3: block-local scan + offset -> g_rowstart -----------------------
__global__ void __launch_bounds__(256) scan_final_kernel() {
    __shared__ int wsum[8];
    int b = blockIdx.x, tid = threadIdx.x, lane = tid & 31, wid = tid >> 5;
    int i0 = b * SCHUNK + tid * 4;
    int v0 = (i0     < NN) ? g_cnt[i0]     : 0;
    int v1 = (i0 + 1 < NN) ? g_cnt[i0 + 1] : 0;
    int v2 = (i0 + 2 < NN) ? g_cnt[i0 + 2] : 0;
    int v3 = (i0 + 3 < NN) ? g_cnt[i0 + 3] : 0;
    int ts = v0 + v1 + v2 + v3;
    int incl = ts;
    #pragma unroll
    for (int off = 1; off < 32; off <<= 1) {
        int t = __shfl_up_sync(0xffffffffu, incl, off);
        if (lane >= off) incl += t;
    }
    if (lane == 31) wsum[wid] = incl;
    __syncthreads();
    int woff = 0;
    for (int w = 0; w < wid; w++) woff += wsum[w];
    int e0 = g_blockoff[b] + woff + (incl - ts);
    int e1 = e0 + v0, e2 = e1 + v1, e3 = e2 + v2;
    if (i0     < NN) g_rowstart[i0]     = e0;
    if (i0 + 1 < NN) g_rowstart[i0 + 1] = e1;
    if (i0 + 2 < NN) g_rowstart[i0 + 2] = e2;
    if (i0 + 3 < NN) g_rowstart[i0 + 3] = e3;
    if (b == 0 && tid == 0) g_rowstart[NN] = EE;   // total is compile-time known
}

__global__ void scatter_kernel(const int* __restrict__ src,
                               const int* __restrict__ dst) {
    int e = blockIdx.x * blockDim.x + threadIdx.x;
    if (e < EE) {
        int d = dst[e];
        int pos = g_rowstart[d] + atomicAdd(&g_fill[d], 1);
        g_csr[pos] = src[e];
    }
}

// ---------------- GEMM 1: y = (emb[x_ids] @ W1) * dinv  (128 -> 64) ---------
__global__ void __launch_bounds__(192) gemm1_kernel(const int* __restrict__ x_ids,
                                                    const float* __restrict__ emb,
                                                    const float* __restrict__ W) {
    __shared__ float Wt[64 * 130];
    __shared__ float xs[24 * 128];
    __shared__ int ids[24];
    int tid = threadIdx.x;
    for (int i = tid; i < EMB_D * HID_D; i += 192) {
        int k = i >> 6, f = i & 63;
        Wt[f * 130 + k] = W[i];
    }
    int grp = tid >> 6, f = tid & 63;
    float* xwf = reinterpret_cast<float*>(g_xw);
    for (int nb = blockIdx.x * 24; nb < NN; nb += gridDim.x * 24) {
        __syncthreads();
        if (tid < 24) { int n = nb + tid; ids[tid] = (n < NN) ? x_ids[n] : 0; }
        __syncthreads();
        for (int i = tid; i < 24 * 128; i += 192) {
            int nl = i >> 7, k = i & 127;
            xs[i] = emb[ids[nl] * 128 + k];
        }
        __syncthreads();
        unsigned long long acc[8];
        #pragma unroll
        for (int n = 0; n < 8; n++) acc[n] = 0ull;
        const float* xb  = &xs[(grp * 8) * 128];
        const float* wrw = &Wt[f * 130];
        #pragma unroll 4
        for (int kp = 0; kp < 64; kp++) {
            unsigned long long w2 =
                *reinterpret_cast<const unsigned long long*>(&wrw[2 * kp]);
            #pragma unroll
            for (int n = 0; n < 8; n++) {
                unsigned long long x2 =
                    *reinterpret_cast<const unsigned long long*>(&xb[n * 128 + 2 * kp]);
                fma2(acc[n], w2, x2);
            }
        }
        #pragma unroll
        for (int n = 0; n < 8; n++) {
            int node = nb + grp * 8 + n;
            if (node < NN) {
                float lo = __uint_as_float((unsigned)(acc[n] & 0xffffffffu));
                float hi = __uint_as_float((unsigned)(acc[n] >> 32));
                xwf[node * 64 + f] = (lo + hi) * g_dinv[node];
            }
        }
    }
}

// ---------------- GEMM 64->64: y = (g_h @ W) * dinv --------------------------
__global__ void __launch_bounds__(256) gemm64_kernel(const float* __restrict__ W) {
    __shared__ float Wt[64 * 66];
    __shared__ float xs[32 * 64];
    int tid = threadIdx.x;
    for (int i = tid; i < 64 * 64; i += 256) {
        int k = i >> 6, f = i & 63;
        Wt[f * 66 + k] = W[i];
    }
    int grp = tid >> 6, f = tid & 63;
    const float* X = reinterpret_cast<const float*>(g_h);
    float* xwf = reinterpret_cast<float*>(g_xw);
    for (int nb = blockIdx.x * 32; nb < NN; nb += gridDim.x * 32) {
        __syncthreads();
        for (int i = tid; i < 32 * 64; i += 256) {
            int nl = i >> 6, k = i & 63;
            int n = nb + nl;
            xs[i] = (n < NN) ? X[n * 64 + k] : 0.f;
        }
        __syncthreads();
        unsigned long long acc[8];
        #pragma unroll
        for (int n = 0; n < 8; n++) acc[n] = 0ull;
        const float* xb  = &xs[(grp * 8) * 64];
        const float* wrw = &Wt[f * 66];
        #pragma unroll 4
        for (int kp = 0; kp < 32; kp++) {
            unsigned long long w2 =
                *reinterpret_cast<const unsigned long long*>(&wrw[2 * kp]);
            #pragma unroll
            for (int n = 0; n < 8; n++) {
                unsigned long long x2 =
                    *reinterpret_cast<const unsigned long long*>(&xb[n * 64 + 2 * kp]);
                fma2(acc[n], w2, x2);
            }
        }
        #pragma unroll
        for (int n = 0; n < 8; n++) {
            int node = nb + grp * 8 + n;
            if (node < NN) {
                float lo = __uint_as_float((unsigned)(acc[n] & 0xffffffffu));
                float hi = __uint_as_float((unsigned)(acc[n] >> 32));
                xwf[node * 64 + f] = (lo + hi) * g_dinv[node];
            }
        }
    }
}

// ---------------- CSR gather: h = relu(dinv*(y_self + sum y[src]) + b) ------
// 16 threads per node, one float4 per thread. Edge loop unrolled x4 with
// software-pipelined index prefetch (idx batch i+1 loads while vals of batch i
// are outstanding). LAST: accumulate into pooled sums instead of writing g_h.
template<bool LAST>
__global__ void gather_kernel(const float* __restrict__ bias,
                              const int* __restrict__ batch) {
    int t = blockIdx.x * blockDim.x + threadIdx.x;
    int node = t >> 4, c = t & 15;
    if (node >= NN) return;
    const float4* __restrict__ y = g_xw;
    float4 a = y[node * 16 + c];                  // self term
    int p  = g_rowstart[node];
    int pe = g_rowstart[node + 1];
    int s0, s1, s2, s3;
    bool have = (p + 4 <= pe);
    if (have) {
        s0 = g_csr[p]; s1 = g_csr[p + 1]; s2 = g_csr[p + 2]; s3 = g_csr[p + 3];
    }
    for (; p + 8 <= pe; p += 4) {
        int t0 = g_csr[p + 4], t1 = g_csr[p + 5], t2 = g_csr[p + 6], t3 = g_csr[p + 7];
        float4 v0 = y[s0 * 16 + c];
        float4 v1 = y[s1 * 16 + c];
        float4 v2 = y[s2 * 16 + c];
        float4 v3 = y[s3 * 16 + c];
        v0.x += v1.x; v0.y += v1.y; v0.z += v1.z; v0.w += v1.w;
        v2.x += v3.x; v2.y += v3.y; v2.z += v3.z; v2.w += v3.w;
        a.x += v0.x + v2.x; a.y += v0.y + v2.y;
        a.z += v0.z + v2.z; a.w += v0.w + v2.w;
        s0 = t0; s1 = t1; s2 = t2; s3 = t3;
    }
    if (have) {
        float4 v0 = y[s0 * 16 + c];
        float4 v1 = y[s1 * 16 + c];
        float4 v2 = y[s2 * 16 + c];
        float4 v3 = y[s3 * 16 + c];
        v0.x += v1.x; v0.y += v1.y; v0.z += v1.z; v0.w += v1.w;
        v2.x += v3.x; v2.y += v3.y; v2.z += v3.z; v2.w += v3.w;
        a.x += v0.x + v2.x; a.y += v0.y + v2.y;
        a.z += v0.z + v2.z; a.w += v0.w + v2.w;
        p += 4;
    }
    for (; p < pe; ++p) {
        int s = g_csr[p];
        float4 v = y[s * 16 + c];
        a.x += v.x; a.y += v.y; a.z += v.z; a.w += v.w;
    }
    float dn = g_dinv[node];
    float4 bb = reinterpret_cast<const float4*>(bias)[c];
    a.x = fmaxf(fmaf(a.x, dn, bb.x), 0.f);
    a.y = fmaxf(fmaf(a.y, dn, bb.y), 0.f);
    a.z = fmaxf(fmaf(a.z, dn, bb.z), 0.f);
    a.w = fmaxf(fmaf(a.w, dn, bb.w), 0.f);
    if (!LAST) {
        g_h[node * 16 + c] = a;
    } else {
        int g = batch[node];
        float* pp = reinterpret_cast<float*>(g_pooled) + g * 64 + c * 4;
        atomicAdd(pp + 0, a.x);
        atomicAdd(pp + 1, a.y);
        atomicAdd(pp + 2, a.z);
        atomicAdd(pp + 3, a.w);
    }
}

// ---------------- final MLP + sigmoid (thread per graph) --------------------
__global__ void __launch_bounds__(32) mlp_kernel(const float* __restrict__ Wf1,
                                                 const float* __restrict__ bf1,
                                                 const float* __restrict__ Wf2,
                                                 const float* __restrict__ bf2,
                                                 float* __restrict__ out) {
    __shared__ float Ws[64 * 64];
    __shared__ float b1s[64];
    __shared__ float w2s[64];
    int tid = threadIdx.x;
    for (int i = tid; i < 64 * 64; i += 32) Ws[i] = Wf1[i];
    for (int i = tid; i < 64; i += 32) { b1s[i] = bf1[i]; w2s[i] = Wf2[i]; }
    __syncthreads();
    int g = blockIdx.x * 32 + tid;
    float cnt = fmaxf((float)g_gcount[g], 1.f);
    float inv = 1.f / cnt;
    const float* pooled = reinterpret_cast<const float*>(g_pooled) + g * 64;
    float p[64];
    #pragma unroll
    for (int k = 0; k < 64; k++) p[k] = pooled[k] * inv;
    float o = bf2[0];
    for (int j = 0; j < 64; j++) {
        float hj = b1s[j];
        #pragma unroll
        for (int k = 0; k < 64; k++) hj = fmaf(p[k], Ws[k * 64 + j], hj);
        o = fmaf(fmaxf(hj, 0.f), w2s[j], o);
    }
    out[g] = 1.f / (1.f + expf(-o));
}

// ---------------- launch ----------------------------------------------------
extern "C" void kernel_launch(void* const* d_in, const int* in_sizes, int n_in,
                              void* d_out, int out_size) {
    const int*   x_ids = (const int*)d_in[0];
    const int*   ei    = (const int*)d_in[1];
    const int*   batch = (const int*)d_in[2];
    const float* emb   = (const float*)d_in[3];
    const float* W1    = (const float*)d_in[4];
    const float* b1    = (const float*)d_in[5];
    const float* W2    = (const float*)d_in[6];
    const float* b2    = (const float*)d_in[7];
    const float* W3    = (const float*)d_in[8];
    const float* b3    = (const float*)d_in[9];
    const float* Wf1   = (const float*)d_in[10];
    const float* bf1   = (const float*)d_in[11];
    const float* Wf2   = (const float*)d_in[12];
    const float* bf2   = (const float*)d_in[13];
    float* out = (float*)d_out;

    const int* src  = ei;
    const int* dstp = ei + EE;

    int nblkN = (NN + 255) / 256;
    int nblkE = (EE + 255) / 256;
    int nblkG = (NN * 16 + 255) / 256;

    // CSR build, reordered so gemm1 is the 4th launch (ncu captures slot 4).
    // gemm1 needs only g_dinv (from scan_part) + inputs; gather1 still runs
    // after scatter completes.
    zero_kernel<<<nblkN, 256>>>();                 // 1
    hist_kernel<<<nblkE, 256>>>(dstp);             // 2
    scan_part_kernel<<<SNB, 256>>>();              // 3 (also computes g_dinv)
    gemm1_kernel<<<740, 192>>>(x_ids, emb, W1);    // 4  <-- profiled slot
    scan_mid_kernel<<<1, 128>>>();                 // 5
    scan_final_kernel<<<SNB, 256>>>();             // 6
    scatter_kernel<<<nblkE, 256>>>(src, dstp);     // 7
    count_kernel<<<nblkN, 256>>>(batch);           // 8

    // layer 1 aggregation
    gather_kernel<false><<<nblkG, 256>>>(b1, batch);
    // layer 2
    gemm64_kernel<<<1184, 256>>>(W2);
    gather_kernel<false><<<nblkG, 256>>>(b2, batch);
    // layer 3 (+ fused pooling)
    gemm64_kernel<<<1184, 256>>>(W3);
    gather_kernel<true><<<nblkG, 256>>>(b3, batch);

    // head
    mlp_kernel<<<8, 32>>>(Wf1, bf1, Wf2, bf2, out);
}